// round 10
// baseline (speedup 1.0000x reference)
#include <cuda_runtime.h>

#define Bv 8192
#define Nv 256
#define Dv 6
#define Rv 3
#define Hv 32
#define TPB 64

// packed weights: [role*256 + h*8 + {0..5: W1 d, 6: b1, 7: W2}], b2[r] at [768+r]
#define CSTRIDE 256
#define PACK_WORDS (Rv * CSTRIDE + 4)
__device__ __align__(16) float g_pack[PACK_WORDS];
__device__ int g_mask_is_u8;   // 0 = int32 mask, 1 = uint8 mask

__global__ void prep_kernel(const float* __restrict__ W1,
                            const float* __restrict__ b1,
                            const float* __restrict__ W2,
                            const float* __restrict__ b2,
                            const unsigned int* __restrict__ mw) {
    __shared__ int any_gt1;
    const int t = threadIdx.x;
    if (t == 0) any_gt1 = 0;
    __syncthreads();
    int found = 0;
    for (int i = t; i < 4096; i += blockDim.x)   // in-bounds under both mask layouts
        if (mw[i] > 1u) found = 1;
    if (found) any_gt1 = 1;
    __syncthreads();
    if (t == 0) g_mask_is_u8 = any_gt1;

    if (t < Rv * Hv) {
        const int r = t / Hv, h = t % Hv;
        float* dst = g_pack + r * CSTRIDE + h * 8;
        #pragma unroll
        for (int d = 0; d < Dv; d++) dst[d] = W1[r * Dv * Hv + d * Hv + h];
        dst[6] = b1[r * Hv + h];
        dst[7] = W2[r * Hv + h];
    }
    if (t < Rv) g_pack[Rv * CSTRIDE + t] = b2[t];
}

// score of one neighbor (boundary-thread fallback)
__device__ __forceinline__ float mlp_one(const float* __restrict__ wr,
                                         const float x0, const float x1, const float x2,
                                         const float x3, const float x4, const float x5) {
    const float4* wp = (const float4*)wr;
    float acc = 0.0f;
    #pragma unroll
    for (int h = 0; h < Hv; h++) {
        const float4 a = wp[h * 2];
        const float4 c = wp[h * 2 + 1];
        float hv = fmaf(x0, a.x, fmaf(x1, a.y, fmaf(x2, a.z,
                   fmaf(x3, a.w, fmaf(x4, c.x, fmaf(x5, c.y, c.z))))));
        acc = fmaf(fmaxf(hv, 0.0f), c.w, acc);
    }
    return acc;
}

__global__ __launch_bounds__(TPB, 10)
void hmf_encoder_kernel(const float* __restrict__ states,
                        const int*   __restrict__ roles,
                        const void*  __restrict__ maskp,
                        const float* __restrict__ trust,
                        float* __restrict__ out)
{
    __shared__ __align__(16) float  sPack[PACK_WORDS];
    __shared__ __align__(16) float2 sxT2[3 * Nv];   // [k][pos] = (x[2k], x[2k+1]), SORTED
    __shared__ __align__(16) float  s_twS[Nv];      // SORTED order trust
    __shared__ __align__(16) float2 s_eew[Nv];      // (e, e*tw), sorted order
    __shared__ int   s_wcnt[8][4];                  // virtual-warp counts
    __shared__ int   s_woff[8][4];
    __shared__ int   s_tot[4];
    __shared__ float warp_max[2][3];
    __shared__ float sm[4];                         // sm[3] = harmless pad

    const int b    = blockIdx.x;
    const int tid  = threadIdx.x;
    const int lane = tid & 31;
    const int wid  = tid >> 5;    // 0..1
    const size_t base = (size_t)b * Nv;

    // ================= Phase A: load 4 neighbors/thread + counting sort =========
    #pragma unroll
    for (int i = tid; i < PACK_WORDS / 4 + 1; i += TPB)
        if (i < PACK_WORDS / 4) ((float4*)sPack)[i] = ((const float4*)g_pack)[i];

    float2 q[4][3];
    int    bu[4];
    float  tw[4];
    #pragma unroll
    for (int k = 0; k < 4; k++) {
        const int j = tid + k * TPB;
        const float2* xp = (const float2*)(states + base * Dv) + j * 3;
        q[k][0] = xp[0]; q[k][1] = xp[1]; q[k][2] = xp[2];
        const int role = roles[base + j];
        int mk;
        if (g_mask_is_u8) mk = ((const unsigned char*)maskp)[base + j];
        else              mk = ((const int*)maskp)[base + j];
        tw[k] = trust[base + j];
        bu[k] = (mk != 0) ? role : 3;
    }

    unsigned bal[4][4];
    #pragma unroll
    for (int k = 0; k < 4; k++) {
        #pragma unroll
        for (int r = 0; r < 4; r++)
            bal[k][r] = __ballot_sync(0xffffffffu, bu[k] == r);
    }
    if (lane == 0) {
        #pragma unroll
        for (int k = 0; k < 4; k++)
            #pragma unroll
            for (int r = 0; r < 4; r++)
                s_wcnt[k * 2 + wid][r] = __popc(bal[k][r]);
    }
    __syncthreads();

    if (tid < 4) {
        int off = 0;
        #pragma unroll
        for (int w = 0; w < 8; w++) { s_woff[w][tid] = off; off += s_wcnt[w][tid]; }
        s_tot[tid] = off;
    }
    __syncthreads();

    const int sb1 = s_tot[0];
    const int sb2 = sb1 + s_tot[1];
    const int sb3 = sb2 + s_tot[2];

    // scatter 4 neighbors into sorted slots
    {
        const unsigned lt = (1u << lane) - 1u;
        #pragma unroll
        for (int k = 0; k < 4; k++) {
            const int bk = bu[k];
            const unsigned bm = (bk == 0) ? bal[k][0] : (bk == 1) ? bal[k][1]
                              : (bk == 2) ? bal[k][2] : bal[k][3];
            const int bbase = (bk == 0) ? 0 : (bk == 1) ? sb1 : (bk == 2) ? sb2 : sb3;
            const int pos = bbase + s_woff[k * 2 + wid][bk] + __popc(bm & lt);
            sxT2[0 * Nv + pos] = q[k][0];
            sxT2[1 * Nv + pos] = q[k][1];
            sxT2[2 * Nv + pos] = q[k][2];
            s_twS[pos] = tw[k];
        }
    }
    __syncthreads();

    // ================= Phase B: MLP, 4 adjacent sorted positions per thread =====
    const int p = tid * 4;
    const int bk0 = (p >= sb3) ? 3 : (p >= sb2) ? 2 : (p >= sb1) ? 1 : 0;
    const int pe = p + 3;
    const int bk3 = (pe >= sb3) ? 3 : (pe >= sb2) ? 2 : (pe >= sb1) ? 1 : 0;

    // 6 LDS.128: V{k}a covers positions p,p+1; V{k}b covers p+2,p+3
    const float4 V0a = *(const float4*)&sxT2[0 * Nv + p];
    const float4 V0b = *(const float4*)&sxT2[0 * Nv + p + 2];
    const float4 V1a = *(const float4*)&sxT2[1 * Nv + p];
    const float4 V1b = *(const float4*)&sxT2[1 * Nv + p + 2];
    const float4 V2a = *(const float4*)&sxT2[2 * Nv + p];
    const float4 V2b = *(const float4*)&sxT2[2 * Nv + p + 2];

    float sc0 = 0.0f, sc1 = 0.0f, sc2 = 0.0f, sc3 = 0.0f;
    if (bk0 == bk3) {
        if (bk0 < Rv) {   // fast path: one weight stream feeds 4 neighbors
            const float4* wp = (const float4*)sPack + (bk0 << 6);
            float a0 = 0.f, a1 = 0.f, a2 = 0.f, a3 = 0.f;
            #pragma unroll
            for (int h = 0; h < Hv; h++) {
                const float4 a = wp[h * 2];       // warp-uniform broadcast
                const float4 c = wp[h * 2 + 1];
                float h0 = fmaf(V0a.x, a.x, fmaf(V0a.y, a.y, fmaf(V1a.x, a.z,
                           fmaf(V1a.y, a.w, fmaf(V2a.x, c.x, fmaf(V2a.y, c.y, c.z))))));
                float h1 = fmaf(V0a.z, a.x, fmaf(V0a.w, a.y, fmaf(V1a.z, a.z,
                           fmaf(V1a.w, a.w, fmaf(V2a.z, c.x, fmaf(V2a.w, c.y, c.z))))));
                float h2 = fmaf(V0b.x, a.x, fmaf(V0b.y, a.y, fmaf(V1b.x, a.z,
                           fmaf(V1b.y, a.w, fmaf(V2b.x, c.x, fmaf(V2b.y, c.y, c.z))))));
                float h3 = fmaf(V0b.z, a.x, fmaf(V0b.w, a.y, fmaf(V1b.z, a.z,
                           fmaf(V1b.w, a.w, fmaf(V2b.z, c.x, fmaf(V2b.w, c.y, c.z))))));
                a0 = fmaf(fmaxf(h0, 0.0f), c.w, a0);
                a1 = fmaf(fmaxf(h1, 0.0f), c.w, a1);
                a2 = fmaf(fmaxf(h2, 0.0f), c.w, a2);
                a3 = fmaf(fmaxf(h3, 0.0f), c.w, a3);
            }
            const float bb = sPack[Rv * CSTRIDE + bk0];
            sc0 = a0 + bb; sc1 = a1 + bb; sc2 = a2 + bb; sc3 = a3 + bb;
        }
    } else {              // rare boundary thread (<= 3 per CTA)
        const int q1 = p + 1, q2 = p + 2;
        const int bkA = (q1 >= sb3) ? 3 : (q1 >= sb2) ? 2 : (q1 >= sb1) ? 1 : 0;
        const int bkB = (q2 >= sb3) ? 3 : (q2 >= sb2) ? 2 : (q2 >= sb1) ? 1 : 0;
        if (bk0 < Rv) sc0 = mlp_one(sPack + bk0 * CSTRIDE, V0a.x, V0a.y, V1a.x, V1a.y, V2a.x, V2a.y)
                            + sPack[Rv * CSTRIDE + bk0];
        if (bkA < Rv) sc1 = mlp_one(sPack + bkA * CSTRIDE, V0a.z, V0a.w, V1a.z, V1a.w, V2a.z, V2a.w)
                            + sPack[Rv * CSTRIDE + bkA];
        if (bkB < Rv) sc2 = mlp_one(sPack + bkB * CSTRIDE, V0b.x, V0b.y, V1b.x, V1b.y, V2b.x, V2b.y)
                            + sPack[Rv * CSTRIDE + bkB];
        if (bk3 < Rv) sc3 = mlp_one(sPack + bk3 * CSTRIDE, V0b.z, V0b.w, V1b.z, V1b.w, V2b.z, V2b.w)
                            + sPack[Rv * CSTRIDE + bk3];
    }

    // per-position buckets (cheap recompute, statically unrollable)
    int pb[4];
    #pragma unroll
    for (int i = 0; i < 4; i++) {
        const int pi = p + i;
        pb[i] = (pi >= sb3) ? 3 : (pi >= sb2) ? 2 : (pi >= sb1) ? 1 : 0;
    }
    const float scv[4] = {sc0, sc1, sc2, sc3};

    // ---- per-role max (zeros included, matching reference semantics) ----
    float vm[Rv] = {0.0f, 0.0f, 0.0f};
    #pragma unroll
    for (int r = 0; r < Rv; r++)
        #pragma unroll
        for (int i = 0; i < 4; i++)
            vm[r] = fmaxf(vm[r], (pb[i] == r) ? scv[i] : 0.0f);
    #pragma unroll
    for (int o = 16; o; o >>= 1) {
        #pragma unroll
        for (int r = 0; r < Rv; r++)
            vm[r] = fmaxf(vm[r], __shfl_xor_sync(0xffffffffu, vm[r], o));
    }
    if (lane == 0) {
        #pragma unroll
        for (int r = 0; r < Rv; r++) warp_max[wid][r] = vm[r];
    }
    __syncthreads();
    if (tid < Rv) sm[tid] = fmaxf(warp_max[0][tid], warp_max[1][tid]);
    if (tid == Rv) sm[Rv] = 0.0f;
    __syncthreads();

    // ---- exponentials: store (e, e*tw) packed, 2x STS.128 ----
    {
        const float4 tws = *(const float4*)&s_twS[p];
        float e[4];
        #pragma unroll
        for (int i = 0; i < 4; i++)
            e[i] = (pb[i] < Rv) ? __expf(scv[i] - sm[pb[i]]) : 0.0f;
        *(float4*)&s_eew[p]     = make_float4(e[0], e[0] * tws.x, e[1], e[1] * tws.y);
        *(float4*)&s_eew[p + 2] = make_float4(e[2], e[2] * tws.z, e[3], e[3] * tws.w);
    }
    __syncthreads();

    // ======== Reduction: warp0 -> segments 0,2; warp1 -> segment 1 ==============
    for (int r = wid; r < Rv; r += 2) {
        const int segLo = (r == 0) ? 0 : (r == 1) ? sb1 : sb2;
        const int segHi = (r == 0) ? sb1 : (r == 1) ? sb2 : sb3;
        float den = 0.0f, ws = 0.0f;
        float num[Dv] = {0.f, 0.f, 0.f, 0.f, 0.f, 0.f};
        for (int n0 = segLo; n0 < segHi; n0 += 32) {
            const int n = n0 + lane;
            if (n < segHi) {
                const float2 ee = s_eew[n];
                const float2 v0 = sxT2[0 * Nv + n];
                const float2 v1 = sxT2[1 * Nv + n];
                const float2 v2 = sxT2[2 * Nv + n];
                den += ee.x;
                ws  += ee.y;
                num[0] = fmaf(ee.y, v0.x, num[0]);
                num[1] = fmaf(ee.y, v0.y, num[1]);
                num[2] = fmaf(ee.y, v1.x, num[2]);
                num[3] = fmaf(ee.y, v1.y, num[3]);
                num[4] = fmaf(ee.y, v2.x, num[4]);
                num[5] = fmaf(ee.y, v2.y, num[5]);
            }
        }
        #pragma unroll
        for (int o = 16; o; o >>= 1) {
            den += __shfl_xor_sync(0xffffffffu, den, o);
            ws  += __shfl_xor_sync(0xffffffffu, ws,  o);
            #pragma unroll
            for (int d = 0; d < Dv; d++)
                num[d] += __shfl_xor_sync(0xffffffffu, num[d], o);
        }
        if (lane < Dv) {
            const float inv = 1.0f / (den + 1e-8f);
            const float wsv = fmaxf(ws * inv, 1e-8f);
            out[(size_t)b * (Rv * Dv) + r * Dv + lane] = num[lane] * inv / wsv;
        }
    }
}

extern "C" void kernel_launch(void* const* d_in, const int* in_sizes, int n_in,
                              void* d_out, int out_size) {
    const float* states = (const float*)d_in[0];
    const int*   roles  = (const int*)d_in[1];
    const void*  maskp  = d_in[2];
    const float* trust  = (const float*)d_in[3];
    const float* W1     = (const float*)d_in[4];
    const float* b1     = (const float*)d_in[5];
    const float* W2     = (const float*)d_in[6];
    const float* b2     = (const float*)d_in[7];
    float* out = (float*)d_out;

    prep_kernel<<<1, 256>>>(W1, b1, W2, b2, (const unsigned int*)maskp);
    hmf_encoder_kernel<<<Bv, TPB>>>(states, roles, maskp, trust, out);
}

// round 11
// speedup vs baseline: 1.5511x; 1.5511x over previous
#include <cuda_runtime.h>

#define Bv 8192
#define Nv 256
#define Dv 6
#define Rv 3
#define Hv 32
#define TPB 128

// packed weights: [role*256 + h*8 + {0..5: W1 d, 6: b1, 7: W2}], b2[r] at [768+r]
#define CSTRIDE 256
#define PACK_WORDS (Rv * CSTRIDE + 4)
__device__ __align__(16) float g_pack[PACK_WORDS];
__device__ int g_mask_is_u8;   // 0 = int32 mask, 1 = uint8 mask

__global__ void prep_kernel(const float* __restrict__ W1,
                            const float* __restrict__ b1,
                            const float* __restrict__ W2,
                            const float* __restrict__ b2,
                            const unsigned int* __restrict__ mw) {
    __shared__ int any_gt1;
    const int t = threadIdx.x;
    if (t == 0) any_gt1 = 0;
    __syncthreads();
    int found = 0;
    for (int i = t; i < 4096; i += blockDim.x)   // in-bounds under both mask layouts
        if (mw[i] > 1u) found = 1;
    if (found) any_gt1 = 1;
    __syncthreads();
    if (t == 0) g_mask_is_u8 = any_gt1;

    if (t < Rv * Hv) {
        const int r = t / Hv, h = t % Hv;
        float* dst = g_pack + r * CSTRIDE + h * 8;
        #pragma unroll
        for (int d = 0; d < Dv; d++) dst[d] = W1[r * Dv * Hv + d * Hv + h];
        dst[6] = b1[r * Hv + h];
        dst[7] = W2[r * Hv + h];
    }
    if (t < Rv) g_pack[Rv * CSTRIDE + t] = b2[t];
}

// score of one neighbor (boundary-thread fallback)
__device__ __forceinline__ float mlp_one(const float* __restrict__ wr,
                                         const float x0, const float x1, const float x2,
                                         const float x3, const float x4, const float x5) {
    const float4* wp = (const float4*)wr;
    float acc = 0.0f;
    #pragma unroll
    for (int h = 0; h < Hv; h++) {
        const float4 a = wp[h * 2];
        const float4 c = wp[h * 2 + 1];
        float hv = fmaf(x0, a.x, fmaf(x1, a.y, fmaf(x2, a.z,
                   fmaf(x3, a.w, fmaf(x4, c.x, fmaf(x5, c.y, c.z))))));
        acc = fmaf(fmaxf(hv, 0.0f), c.w, acc);
    }
    return acc;
}

__global__ __launch_bounds__(TPB, 8)
void hmf_encoder_kernel(const float* __restrict__ states,
                        const int*   __restrict__ roles,
                        const void*  __restrict__ maskp,
                        const float* __restrict__ trust,
                        float* __restrict__ out)
{
    __shared__ __align__(16) float  sPack[PACK_WORDS];
    __shared__ __align__(16) float2 sxT2[3 * Nv];   // [k][pos] = (x[2k], x[2k+1]), SORTED
    __shared__ __align__(16) float  s_twS[Nv];      // SORTED order trust
    __shared__ __align__(16) float  s_part[4][Rv][8]; // per-warp per-role partials
    __shared__ __align__(16) float  s_fin[Rv][8];
    __shared__ int   s_wcnt[8][4];                  // virtual-warp counts
    __shared__ int   s_woff[8][4];
    __shared__ int   s_tot[4];
    __shared__ int   s_base[5];                     // bucket segment starts
    __shared__ float warp_max[4][3];
    __shared__ float sm[Rv];

    const int b    = blockIdx.x;
    const int tid  = threadIdx.x;
    const int lane = tid & 31;
    const int wid  = tid >> 5;    // 0..3
    const size_t base = (size_t)b * Nv;

    // ================= Phase A: load 2 neighbors/thread + counting sort =========
    for (int i = tid; i < PACK_WORDS / 4; i += TPB)
        ((float4*)sPack)[i] = ((const float4*)g_pack)[i];

    // neighbors j0 = tid, j1 = tid + 128 (coalesced LDG.64 x3 each)
    float2 qa0, qa1, qa2, qc0, qc1, qc2;
    {
        const float2* xp = (const float2*)(states + base * Dv) + tid * 3;
        qa0 = xp[0]; qa1 = xp[1]; qa2 = xp[2];
        const float2* yp = xp + TPB * 3;
        qc0 = yp[0]; qc1 = yp[1]; qc2 = yp[2];
    }
    const int role0 = roles[base + tid];
    const int role1 = roles[base + tid + TPB];
    int mk0, mk1;
    if (g_mask_is_u8) {
        mk0 = ((const unsigned char*)maskp)[base + tid];
        mk1 = ((const unsigned char*)maskp)[base + tid + TPB];
    } else {
        mk0 = ((const int*)maskp)[base + tid];
        mk1 = ((const int*)maskp)[base + tid + TPB];
    }
    const float tw0 = trust[base + tid];
    const float tw1 = trust[base + tid + TPB];

    const int bu0 = (mk0 != 0) ? role0 : 3;
    const int bu1 = (mk1 != 0) ? role1 : 3;

    const unsigned a0 = __ballot_sync(0xffffffffu, bu0 == 0);
    const unsigned a1 = __ballot_sync(0xffffffffu, bu0 == 1);
    const unsigned a2 = __ballot_sync(0xffffffffu, bu0 == 2);
    const unsigned a3 = __ballot_sync(0xffffffffu, bu0 == 3);
    const unsigned c0 = __ballot_sync(0xffffffffu, bu1 == 0);
    const unsigned c1 = __ballot_sync(0xffffffffu, bu1 == 1);
    const unsigned c2 = __ballot_sync(0xffffffffu, bu1 == 2);
    const unsigned c3 = __ballot_sync(0xffffffffu, bu1 == 3);
    if (lane == 0) {
        s_wcnt[wid][0] = __popc(a0);  s_wcnt[wid][1] = __popc(a1);
        s_wcnt[wid][2] = __popc(a2);  s_wcnt[wid][3] = __popc(a3);
        s_wcnt[4 + wid][0] = __popc(c0);  s_wcnt[4 + wid][1] = __popc(c1);
        s_wcnt[4 + wid][2] = __popc(c2);  s_wcnt[4 + wid][3] = __popc(c3);
    }
    __syncthreads();

    if (wid == 0) {
        if (lane < 4) {
            int off = 0;
            #pragma unroll
            for (int w = 0; w < 8; w++) { s_woff[w][lane] = off; off += s_wcnt[w][lane]; }
            s_tot[lane] = off;
        }
        __syncwarp();
        if (lane == 0) {
            s_base[0] = 0;
            #pragma unroll
            for (int r = 0; r < 4; r++) s_base[r + 1] = s_base[r] + s_tot[r];
        }
    }
    __syncthreads();

    // scatter both neighbors into sorted slots (x pairs + trust)
    {
        const unsigned lt = (1u << lane) - 1u;
        const unsigned am = (bu0 == 0) ? a0 : (bu0 == 1) ? a1 : (bu0 == 2) ? a2 : a3;
        const unsigned cm = (bu1 == 0) ? c0 : (bu1 == 1) ? c1 : (bu1 == 2) ? c2 : c3;
        const int pos0 = s_base[bu0] + s_woff[wid][bu0]     + __popc(am & lt);
        const int pos1 = s_base[bu1] + s_woff[4 + wid][bu1] + __popc(cm & lt);
        sxT2[0 * Nv + pos0] = qa0;   // 3 STS.64 per neighbor
        sxT2[1 * Nv + pos0] = qa1;
        sxT2[2 * Nv + pos0] = qa2;
        sxT2[0 * Nv + pos1] = qc0;
        sxT2[1 * Nv + pos1] = qc1;
        sxT2[2 * Nv + pos1] = qc2;
        s_twS[pos0] = tw0;
        s_twS[pos1] = tw1;
    }
    __syncthreads();

    // ================= Phase B: MLP, 2 adjacent sorted positions per thread =====
    const int p0 = tid * 2;         // even
    const int p1 = p0 + 1;
    const int bkt0 = (p0 >= s_base[3]) ? 3 : (p0 >= s_base[2]) ? 2 : (p0 >= s_base[1]) ? 1 : 0;
    const int bkt1 = (p1 >= s_base[3]) ? 3 : (p1 >= s_base[2]) ? 2 : (p1 >= s_base[1]) ? 1 : 0;

    // 3 LDS.128: X[k] = {n0.d2k, n0.d2k+1, n1.d2k, n1.d2k+1}
    const float4 X0 = *(const float4*)&sxT2[0 * Nv + p0];
    const float4 X1 = *(const float4*)&sxT2[1 * Nv + p0];
    const float4 X2 = *(const float4*)&sxT2[2 * Nv + p0];

    float sc0 = 0.0f, sc1 = 0.0f;
    if (bkt0 < Rv) {      // shared-role fast path: one weight stream feeds both neighbors
        const float4* wp = (const float4*)sPack + (bkt0 << 6);
        float acc0 = 0.0f, acc1 = 0.0f;
        #pragma unroll
        for (int h = 0; h < Hv; h++) {
            const float4 a = wp[h * 2];       // warp-uniform broadcast
            const float4 c = wp[h * 2 + 1];
            float hv0 = fmaf(X0.x, a.x, fmaf(X0.y, a.y, fmaf(X1.x, a.z,
                        fmaf(X1.y, a.w, fmaf(X2.x, c.x, fmaf(X2.y, c.y, c.z))))));
            float hv1 = fmaf(X0.z, a.x, fmaf(X0.w, a.y, fmaf(X1.z, a.z,
                        fmaf(X1.w, a.w, fmaf(X2.z, c.x, fmaf(X2.w, c.y, c.z))))));
            acc0 = fmaf(fmaxf(hv0, 0.0f), c.w, acc0);
            acc1 = fmaf(fmaxf(hv1, 0.0f), c.w, acc1);
        }
        const float bb = sPack[Rv * CSTRIDE + bkt0];
        sc0 = acc0 + bb;
        sc1 = acc1 + bb;
    }
    if (bkt1 != bkt0) {   // rare boundary thread (<= 3 per CTA)
        sc1 = 0.0f;
        if (bkt1 < Rv)
            sc1 = mlp_one(sPack + bkt1 * CSTRIDE,
                          X0.z, X0.w, X1.z, X1.w, X2.z, X2.w)
                  + sPack[Rv * CSTRIDE + bkt1];
    }

    // ---- per-role max (zeros included, matching reference semantics) ----
    float vm[Rv] = {0.0f, 0.0f, 0.0f};
    if (bkt0 < Rv) vm[bkt0] = fmaxf(vm[bkt0], sc0);
    if (bkt1 < Rv) vm[bkt1] = fmaxf(vm[bkt1], sc1);
    #pragma unroll
    for (int o = 16; o; o >>= 1) {
        #pragma unroll
        for (int r = 0; r < Rv; r++)
            vm[r] = fmaxf(vm[r], __shfl_xor_sync(0xffffffffu, vm[r], o));
    }
    if (lane == 0) {
        #pragma unroll
        for (int r = 0; r < Rv; r++) warp_max[wid][r] = vm[r];
    }
    __syncthreads();
    if (tid < Rv) {
        float m = warp_max[0][tid];
        #pragma unroll
        for (int w = 1; w < 4; w++) m = fmaxf(m, warp_max[w][tid]);
        sm[tid] = m;
    }
    __syncthreads();

    // ---- exponentials + FUSED pooling: per-role predicated warp reductions -----
    {
        const float e0 = (bkt0 < Rv) ? __expf(sc0 - sm[bkt0]) : 0.0f;
        const float e1 = (bkt1 < Rv) ? __expf(sc1 - sm[bkt1]) : 0.0f;
        const float2 twp = *(const float2*)&s_twS[p0];
        const float ew0 = e0 * twp.x;
        const float ew1 = e1 * twp.y;

        #pragma unroll
        for (int r = 0; r < Rv; r++) {
            const bool in0 = (bkt0 == r);
            const bool in1 = (bkt1 == r);
            const unsigned has = __ballot_sync(0xffffffffu, in0 || in1);
            if (has) {
                const float g0 = in0 ? ew0 : 0.0f;
                const float g1 = in1 ? ew1 : 0.0f;
                float v[8];
                v[0] = (in0 ? e0 : 0.0f) + (in1 ? e1 : 0.0f);
                v[1] = g0 + g1;
                v[2] = fmaf(g0, X0.x, g1 * X0.z);
                v[3] = fmaf(g0, X0.y, g1 * X0.w);
                v[4] = fmaf(g0, X1.x, g1 * X1.z);
                v[5] = fmaf(g0, X1.y, g1 * X1.w);
                v[6] = fmaf(g0, X2.x, g1 * X2.z);
                v[7] = fmaf(g0, X2.y, g1 * X2.w);
                #pragma unroll
                for (int o = 16; o; o >>= 1) {
                    #pragma unroll
                    for (int k = 0; k < 8; k++)
                        v[k] += __shfl_xor_sync(0xffffffffu, v[k], o);
                }
                if (lane == 0) {
                    *(float4*)&s_part[wid][r][0] = make_float4(v[0], v[1], v[2], v[3]);
                    *(float4*)&s_part[wid][r][4] = make_float4(v[4], v[5], v[6], v[7]);
                }
            } else if (lane == 0) {
                *(float4*)&s_part[wid][r][0] = make_float4(0.f, 0.f, 0.f, 0.f);
                *(float4*)&s_part[wid][r][4] = make_float4(0.f, 0.f, 0.f, 0.f);
            }
        }
    }
    __syncthreads();

    // ---- final combine: 24 threads sum warp partials, 18 threads write out ----
    if (tid < 24) {
        const int r = tid >> 3, c = tid & 7;
        s_fin[r][c] = s_part[0][r][c] + s_part[1][r][c]
                    + s_part[2][r][c] + s_part[3][r][c];
    }
    __syncthreads();
    if (tid < Rv * Dv) {
        const int r = tid / Dv, d = tid - r * Dv;
        const float den = s_fin[r][0], ws = s_fin[r][1];
        const float inv = 1.0f / (den + 1e-8f);
        const float wsv = fmaxf(ws * inv, 1e-8f);
        out[(size_t)b * (Rv * Dv) + tid] = s_fin[r][2 + d] * inv / wsv;
    }
}

extern "C" void kernel_launch(void* const* d_in, const int* in_sizes, int n_in,
                              void* d_out, int out_size) {
    const float* states = (const float*)d_in[0];
    const int*   roles  = (const int*)d_in[1];
    const void*  maskp  = d_in[2];
    const float* trust  = (const float*)d_in[3];
    const float* W1     = (const float*)d_in[4];
    const float* b1     = (const float*)d_in[5];
    const float* W2     = (const float*)d_in[6];
    const float* b2     = (const float*)d_in[7];
    float* out = (float*)d_out;

    prep_kernel<<<1, 256>>>(W1, b1, W2, b2, (const unsigned int*)maskp);
    hmf_encoder_kernel<<<Bv, TPB>>>(states, roles, maskp, trust, out);
}